// round 11
// baseline (speedup 1.0000x reference)
#include <cuda_runtime.h>

#define C 16
#define HEADS 2
#define HD 8
#define WS 8
#define HID 64
#define HH 512
#define WW 512
#define NTOK 64
#define CTAW 4          // windows per CTA
#define NTHR 128

typedef unsigned long long u64;

// -------- folded weights (prep kernel -> main kernel) --------
__device__ float g_qkvw[48 * C];   // aff1-folded qkv weight; Q rows pre-scaled by hd^-0.5*log2e
__device__ float g_qkvb[48];
__device__ float g_fc1w[HID * C];  // aff2-folded fc1 weight
__device__ float g_fc1b[HID];
__device__ float g_fc2wt[HID * C]; // fc2_w transposed: [j][c]

__device__ __forceinline__ u64 pack2(float a, float b) {
    u64 r; asm("mov.b64 %0, {%1,%2};" : "=l"(r) : "f"(a), "f"(b)); return r;
}
__device__ __forceinline__ void unpack2(u64 v, float& a, float& b) {
    asm("mov.b64 {%0,%1}, %2;" : "=f"(a), "=f"(b) : "l"(v));
}
__device__ __forceinline__ void ffma2(u64& d, u64 a, u64 b) {
    asm("fma.rn.f32x2 %0, %1, %2, %0;" : "+l"(d) : "l"(a), "l"(b));
}
__device__ __forceinline__ u64 fmul2(u64 a, u64 b) {
    u64 r; asm("mul.rn.f32x2 %0, %1, %2;" : "=l"(r) : "l"(a), "l"(b)); return r;
}
__device__ __forceinline__ float fexp2(float x) {   // 2^x
    float r; asm("ex2.approx.f32 %0, %1;" : "=f"(r) : "f"(x)); return r;
}
__device__ __forceinline__ float frcp(float x) {
    float r; asm("rcp.approx.f32 %0, %1;" : "=f"(r) : "f"(x)); return r;
}
__device__ __forceinline__ float ftanh(float x) {
    float r; asm("tanh.approx.f32 %0, %1;" : "=f"(r) : "f"(x)); return r;
}
__device__ __forceinline__ float hsum2(u64 a, u64 b) {
    float x0, x1, y0, y1; unpack2(a, x0, x1); unpack2(b, y0, y1);
    return (x0 + x1) + (y0 + y1);
}

// 16-wide dot for TWO tokens sharing one weight row (4x LDS.128, 16 ffma2)
__device__ __forceinline__ void dot16x2(const u64* a0, const u64* a1,
                                        const float* w, float& r0, float& r1) {
    const ulonglong2* wp = reinterpret_cast<const ulonglong2*>(w);
    ulonglong2 w0 = wp[0], w1 = wp[1], w2 = wp[2], w3 = wp[3];
    u64 p0 = 0, q0 = 0, p1 = 0, q1 = 0;
    ffma2(p0, a0[0], w0.x); ffma2(q0, a0[1], w0.y);
    ffma2(p0, a0[2], w1.x); ffma2(q0, a0[3], w1.y);
    ffma2(p0, a0[4], w2.x); ffma2(q0, a0[5], w2.y);
    ffma2(p0, a0[6], w3.x); ffma2(q0, a0[7], w3.y);
    ffma2(p1, a1[0], w0.x); ffma2(q1, a1[1], w0.y);
    ffma2(p1, a1[2], w1.x); ffma2(q1, a1[3], w1.y);
    ffma2(p1, a1[4], w2.x); ffma2(q1, a1[5], w2.y);
    ffma2(p1, a1[6], w3.x); ffma2(q1, a1[7], w3.y);
    r0 = hsum2(p0, q0); r1 = hsum2(p1, q1);
}

// ---------------- prep: fold aff layers into GEMM weights ----------------
__global__ void prep_kernel(
    const float* __restrict__ alpha1, const float* __restrict__ beta1, const float* __restrict__ color1,
    const float* __restrict__ qkv_w, const float* __restrict__ qkv_b,
    const float* __restrict__ alpha2, const float* __restrict__ beta2, const float* __restrict__ color2,
    const float* __restrict__ fc1_w, const float* __restrict__ fc1_b,
    const float* __restrict__ fc2_w)
{
    const int t = threadIdx.x;   // 256 threads
    const float QSCL = 0.35355339059327373f * 1.4426950408889634f; // hd^-0.5 * log2(e)
    for (int e = t; e < 48 * C; e += 256) {
        int j = e >> 4, c = e & 15;
        float acc = 0.f;
        for (int k = 0; k < C; k++)
            acc += qkv_w[j * C + k] * alpha1[k] * color1[k * C + c];
        g_qkvw[e] = (j < 16) ? acc * QSCL : acc;
    }
    if (t < 48) {
        float bb = qkv_b[t];
        for (int k = 0; k < C; k++) bb += qkv_w[t * C + k] * beta1[k];
        g_qkvb[t] = (t < 16) ? bb * QSCL : bb;
    }
    for (int e = t; e < HID * C; e += 256) {
        int j = e >> 4, c = e & 15;
        float acc = 0.f;
        for (int k = 0; k < C; k++)
            acc += fc1_w[j * C + k] * alpha2[k] * color2[k * C + c];
        g_fc1w[e] = acc;
    }
    if (t < HID) {
        float bb = fc1_b[t];
        for (int k = 0; k < C; k++) bb += fc1_w[t * C + k] * beta2[k];
        g_fc1b[t] = bb;
    }
    for (int e = t; e < HID * C; e += 256) {
        int j = e >> 4, c = e & 15;
        g_fc2wt[e] = fc2_w[c * HID + j];
    }
}

// ---------------- main fused kernel: 128 threads = 4 windows ----------------
__global__ __launch_bounds__(NTHR, 4) void swin_fused_kernel(
    const float* __restrict__ x,
    const float* __restrict__ pos_w, const float* __restrict__ pos_b,
    const float* __restrict__ proj_w, const float* __restrict__ proj_b,
    const float* __restrict__ fc2_b,
    float* __restrict__ out)
{
    // union: halo [16][10][34] (5440 f)  THEN  K[4w][2h][64][8] + V same (8192 f)
    __shared__ __align__(16) float sh_dyn[8192];
    __shared__ __align__(16) float sh_qkvw[48 * C];
    __shared__ __align__(16) float sh_projw[C * C];
    __shared__ __align__(16) float sh_fc1w[HID * C];
    __shared__ __align__(16) float sh_fc2wt[HID * C];
    __shared__ __align__(16) float sh_posw[C * 9];
    __shared__ float sh_qkvb[48], sh_projb[C], sh_fc1b[HID], sh_fc2b[C], sh_posb[C];

    const int tid = threadIdx.x;
    const int b  = blockIdx.z;
    const int y0 = blockIdx.y * WS;
    const int x0 = blockIdx.x * (CTAW * WS);   // 32 columns per CTA

    // ---- cooperative weight loads ----
    for (int i = tid; i < HID * C; i += NTHR) {
        sh_fc1w[i]  = g_fc1w[i];
        sh_fc2wt[i] = g_fc2wt[i];
    }
    for (int i = tid; i < 48 * C; i += NTHR) sh_qkvw[i] = g_qkvw[i];
    for (int i = tid; i < C * C; i += NTHR)  sh_projw[i] = proj_w[i];
    for (int i = tid; i < C * 9; i += NTHR)  sh_posw[i] = pos_w[i];
    if (tid < 48) sh_qkvb[tid] = g_qkvb[tid];
    if (tid < HID) sh_fc1b[tid] = g_fc1b[tid];
    if (tid < C) {
        sh_projb[tid] = proj_b[tid];
        sh_fc2b[tid]  = fc2_b[tid];
        sh_posb[tid]  = pos_b[tid];
    }

    // ---- halo load: [C][10][34] with zero padding ----
    const float* xb = x + (size_t)b * C * HH * WW;
#define HALO(c, r, cc) sh_dyn[(c) * 340 + (r) * 34 + (cc)]
    for (int i = tid; i < C * 340; i += NTHR) {
        int c = i / 340, rem = i - c * 340;
        int r = rem / 34, cc = rem - r * 34;
        int gy = y0 - 1 + r, gx = x0 - 1 + cc;
        float v = 0.f;
        if ((unsigned)gy < HH && (unsigned)gx < WW)
            v = xb[c * (HH * WW) + gy * WW + gx];
        sh_dyn[i] = v;
    }
    __syncthreads();

    // warp w handles window w; thread owns tokens (ty0,tx) and (ty0+4,tx)
    const int w = tid >> 5, lane = tid & 31;
    const int ty0 = lane >> 3, tx = lane & 7;
    const int hc = w * 8 + tx;

    // ---- depthwise 3x3 conv + residual + bias -> exact fp32 shortcut ----
    float s0[C], s1[C];
#pragma unroll
    for (int c = 0; c < C; c++) {
        float a0 = HALO(c, ty0 + 1, hc + 1) + sh_posb[c];
        float a1 = HALO(c, ty0 + 5, hc + 1) + sh_posb[c];
#pragma unroll
        for (int di = 0; di < 3; di++)
#pragma unroll
            for (int dj = 0; dj < 3; dj++) {
                float wgt = sh_posw[c * 9 + di * 3 + dj];
                a0 = fmaf(HALO(c, ty0 + di,     hc + dj), wgt, a0);
                a1 = fmaf(HALO(c, ty0 + 4 + di, hc + dj), wgt, a1);
            }
        s0[c] = a0; s1[c] = a1;
    }
    __syncthreads();   // all halo reads done -> sh_dyn becomes K/V

    float* sh_k = sh_dyn;              // [((w*2+h)*64 + m)*8 + d]
    float* sh_v = sh_dyn + 4096;

    u64 sp0[8], sp1[8];
#pragma unroll
    for (int i = 0; i < 8; i++) {
        sp0[i] = pack2(s0[2 * i], s0[2 * i + 1]);
        sp1[i] = pack2(s1[2 * i], s1[2 * i + 1]);
    }

    // ---- qkv directly from shortcut (aff1 folded); Q rows pre-scaled ----
    u64 qp0[2][4], qp1[2][4];
#pragma unroll
    for (int j = 0; j < C; j += 2) {
        float ra0, ra1, rb0, rb1;
        dot16x2(sp0, sp1, &sh_qkvw[j * C], ra0, ra1);
        dot16x2(sp0, sp1, &sh_qkvw[(j + 1) * C], rb0, rb1);
        qp0[j >> 3][(j & 7) >> 1] = pack2(ra0 + sh_qkvb[j], rb0 + sh_qkvb[j + 1]);
        qp1[j >> 3][(j & 7) >> 1] = pack2(ra1 + sh_qkvb[j], rb1 + sh_qkvb[j + 1]);
    }
#pragma unroll 2
    for (int j = 0; j < C; j += 2) {          // K
        float ra0, ra1, rb0, rb1;
        dot16x2(sp0, sp1, &sh_qkvw[(16 + j) * C], ra0, ra1);
        dot16x2(sp0, sp1, &sh_qkvw[(16 + j + 1) * C], rb0, rb1);
        int h = j >> 3, d = j & 7;
        float* base = &sh_k[((w * 2 + h) * 64 + lane) * 8 + d];
        *(float2*)base         = make_float2(ra0 + sh_qkvb[16 + j], rb0 + sh_qkvb[16 + j + 1]);
        *(float2*)(base + 256) = make_float2(ra1 + sh_qkvb[16 + j], rb1 + sh_qkvb[16 + j + 1]);
    }
#pragma unroll 2
    for (int j = 0; j < C; j += 2) {          // V
        float ra0, ra1, rb0, rb1;
        dot16x2(sp0, sp1, &sh_qkvw[(32 + j) * C], ra0, ra1);
        dot16x2(sp0, sp1, &sh_qkvw[(32 + j + 1) * C], rb0, rb1);
        int h = j >> 3, d = j & 7;
        float* base = &sh_v[((w * 2 + h) * 64 + lane) * 8 + d];
        *(float2*)base         = make_float2(ra0 + sh_qkvb[32 + j], rb0 + sh_qkvb[32 + j + 1]);
        *(float2*)(base + 256) = make_float2(ra1 + sh_qkvb[32 + j], rb1 + sh_qkvb[32 + j + 1]);
    }
    __syncwarp();   // K/V are warp-private (warp == window)

    // ---- window attention; logits already in log2 domain -> bare ex2 ----
    u64 aop0[8], aop1[8];
#pragma unroll
    for (int h = 0; h < HEADS; h++) {
        const ulonglong2* kb = (const ulonglong2*)&sh_k[(w * 2 + h) * 64 * 8];
        const ulonglong2* vb = (const ulonglong2*)&sh_v[(w * 2 + h) * 64 * 8];
        float sA0 = 0.f, sB0 = 0.f, sA1 = 0.f, sB1 = 0.f;
        u64 o0[4] = {0, 0, 0, 0}, o1[4] = {0, 0, 0, 0};
#pragma unroll 2
        for (int m = 0; m < NTOK; m++) {
            ulonglong2 ka = kb[2 * m], kc = kb[2 * m + 1];
            u64 d0a = 0, d0b = 0, d1a = 0, d1b = 0;
            ffma2(d0a, qp0[h][0], ka.x); ffma2(d0b, qp0[h][1], ka.y);
            ffma2(d0a, qp0[h][2], kc.x); ffma2(d0b, qp0[h][3], kc.y);
            ffma2(d1a, qp1[h][0], ka.x); ffma2(d1b, qp1[h][1], ka.y);
            ffma2(d1a, qp1[h][2], kc.x); ffma2(d1b, qp1[h][3], kc.y);
            float p0 = fexp2(hsum2(d0a, d0b));
            float p1 = fexp2(hsum2(d1a, d1b));
            if (m & 1) { sB0 += p0; sB1 += p1; }
            else       { sA0 += p0; sA1 += p1; }
            ulonglong2 va = vb[2 * m], vc = vb[2 * m + 1];
            u64 pp0 = pack2(p0, p0), pp1 = pack2(p1, p1);
            ffma2(o0[0], pp0, va.x); ffma2(o0[1], pp0, va.y);
            ffma2(o0[2], pp0, vc.x); ffma2(o0[3], pp0, vc.y);
            ffma2(o1[0], pp1, va.x); ffma2(o1[1], pp1, va.y);
            ffma2(o1[2], pp1, vc.x); ffma2(o1[3], pp1, vc.y);
        }
        float r0 = frcp(sA0 + sB0), r1 = frcp(sA1 + sB1);
        u64 rr0 = pack2(r0, r0), rr1 = pack2(r1, r1);
#pragma unroll
        for (int i = 0; i < 4; i++) {
            aop0[h * 4 + i] = fmul2(o0[i], rr0);
            aop1[h * 4 + i] = fmul2(o1[i], rr1);
        }
    }

    // ---- proj + residual -> x2 ----
    u64 x2p0[8], x2p1[8];
#pragma unroll
    for (int j = 0; j < C; j += 2) {
        float ra0, ra1, rb0, rb1;
        dot16x2(aop0, aop1, &sh_projw[j * C], ra0, ra1);
        dot16x2(aop0, aop1, &sh_projw[(j + 1) * C], rb0, rb1);
        float sa0, sa1, sb0, sb1;
        unpack2(sp0[j >> 1], sa0, sb0);
        unpack2(sp1[j >> 1], sa1, sb1);
        x2p0[j >> 1] = pack2(sa0 + ra0 + sh_projb[j], sb0 + rb0 + sh_projb[j + 1]);
        x2p1[j >> 1] = pack2(sa1 + ra1 + sh_projb[j], sb1 + rb1 + sh_projb[j + 1]);
    }

    // ---- MLP: fc1 (aff2 folded) -> GELU -> fc2 ----
    u64 fo0[8] = {0, 0, 0, 0, 0, 0, 0, 0}, fo1[8] = {0, 0, 0, 0, 0, 0, 0, 0};
#pragma unroll 2
    for (int j = 0; j < HID; j++) {
        float t0, t1;
        dot16x2(x2p0, x2p1, &sh_fc1w[j * C], t0, t1);
        t0 += sh_fc1b[j]; t1 += sh_fc1b[j];
        float u0 = 0.7978845608028654f * fmaf(0.044715f * t0, t0 * t0, t0);
        float u1 = 0.7978845608028654f * fmaf(0.044715f * t1, t1 * t1, t1);
        float g0 = 0.5f * t0 * (1.f + ftanh(u0));
        float g1 = 0.5f * t1 * (1.f + ftanh(u1));
        const ulonglong2* wp = (const ulonglong2*)&sh_fc2wt[j * C];
        ulonglong2 w0 = wp[0], w1 = wp[1], w2 = wp[2], w3 = wp[3];
        u64 gg0 = pack2(g0, g0), gg1 = pack2(g1, g1);
        ffma2(fo0[0], gg0, w0.x); ffma2(fo0[1], gg0, w0.y);
        ffma2(fo0[2], gg0, w1.x); ffma2(fo0[3], gg0, w1.y);
        ffma2(fo0[4], gg0, w2.x); ffma2(fo0[5], gg0, w2.y);
        ffma2(fo0[6], gg0, w3.x); ffma2(fo0[7], gg0, w3.y);
        ffma2(fo1[0], gg1, w0.x); ffma2(fo1[1], gg1, w0.y);
        ffma2(fo1[2], gg1, w1.x); ffma2(fo1[3], gg1, w1.y);
        ffma2(fo1[4], gg1, w2.x); ffma2(fo1[5], gg1, w2.y);
        ffma2(fo1[6], gg1, w3.x); ffma2(fo1[7], gg1, w3.y);
    }

    // ---- residual + NCHW write (2 tokens) ----
    float* ob = out + (size_t)b * C * HH * WW;
    const int gx = x0 + w * 8 + tx;
    const int gy0 = y0 + ty0, gy1 = y0 + ty0 + 4;
#pragma unroll
    for (int i = 0; i < 8; i++) {
        float lo0, hi0, lo1, hi1, xa0, xb0, xa1, xb1;
        unpack2(fo0[i], lo0, hi0); unpack2(fo1[i], lo1, hi1);
        unpack2(x2p0[i], xa0, xb0); unpack2(x2p1[i], xa1, xb1);
        int c0 = 2 * i;
        ob[c0 * (HH * WW) + gy0 * WW + gx]       = xa0 + sh_fc2b[c0]     + lo0;
        ob[(c0 + 1) * (HH * WW) + gy0 * WW + gx] = xb0 + sh_fc2b[c0 + 1] + hi0;
        ob[c0 * (HH * WW) + gy1 * WW + gx]       = xa1 + sh_fc2b[c0]     + lo1;
        ob[(c0 + 1) * (HH * WW) + gy1 * WW + gx] = xb1 + sh_fc2b[c0 + 1] + hi1;
    }
#undef HALO
}

extern "C" void kernel_launch(void* const* d_in, const int* in_sizes, int n_in,
                              void* d_out, int out_size) {
    (void)n_in; (void)out_size;
    const float* x      = (const float*)d_in[0];
    const float* pos_w  = (const float*)d_in[1];
    const float* pos_b  = (const float*)d_in[2];
    const float* alpha1 = (const float*)d_in[3];
    const float* beta1  = (const float*)d_in[4];
    const float* color1 = (const float*)d_in[5];
    const float* qkv_w  = (const float*)d_in[6];
    const float* qkv_b  = (const float*)d_in[7];
    const float* proj_w = (const float*)d_in[8];
    const float* proj_b = (const float*)d_in[9];
    const float* alpha2 = (const float*)d_in[10];
    const float* beta2  = (const float*)d_in[11];
    const float* color2 = (const float*)d_in[12];
    const float* fc1_w  = (const float*)d_in[13];
    const float* fc1_b  = (const float*)d_in[14];
    const float* fc2_w  = (const float*)d_in[15];
    const float* fc2_b  = (const float*)d_in[16];

    prep_kernel<<<1, 256>>>(alpha1, beta1, color1, qkv_w, qkv_b,
                            alpha2, beta2, color2, fc1_w, fc1_b, fc2_w);

    int B = in_sizes[0] / (C * HH * WW);
    dim3 grid(WW / (CTAW * WS), HH / WS, B);
    swin_fused_kernel<<<grid, NTHR>>>(
        x, pos_w, pos_b, proj_w, proj_b, fc2_b, (float*)d_out);
}

// round 14
// speedup vs baseline: 1.6190x; 1.6190x over previous
#include <cuda_runtime.h>
#include <cuda_bf16.h>

#define C 16
#define HEADS 2
#define HD 8
#define WS 8
#define HID 64
#define HH 512
#define WW 512
#define NTOK 64
#define CTAW 4
#define NTHR 128
#define HW2 (HH * WW)

// ---- folded / repacked weights (prep kernel -> main kernel) ----
// B operands stored [n][k] row-major bf16 with padded k-stride for bank-conflict-free frag loads.
__device__ __nv_bfloat16 gB_qkv[48 * 24];   // qkv' (aff1 folded); Q rows pre-scaled hd^-.5*log2e
__device__ float         gQKVb[48];
__device__ __nv_bfloat16 gB_fc1[64 * 24];   // fc1' (aff2 folded)
__device__ float         gFC1b[64];
__device__ __nv_bfloat16 gB_proj[16 * 24];
__device__ __nv_bfloat16 gB_fc2[16 * 72];   // [out n][in k], k-stride 72

__device__ __forceinline__ float fexp2(float x) {
    float r; asm("ex2.approx.f32 %0, %1;" : "=f"(r) : "f"(x)); return r;
}
__device__ __forceinline__ float frcp(float x) {
    float r; asm("rcp.approx.f32 %0, %1;" : "=f"(r) : "f"(x)); return r;
}
__device__ __forceinline__ float ftanh(float x) {
    float r; asm("tanh.approx.f32 %0, %1;" : "=f"(r) : "f"(x)); return r;
}
// pack {lo, hi} floats -> bf16x2 (lo in lower 16 bits)
__device__ __forceinline__ unsigned bfp(float lo, float hi) {
    unsigned d; asm("cvt.rn.bf16x2.f32 %0, %1, %2;" : "=r"(d) : "f"(hi), "f"(lo)); return d;
}
__device__ __forceinline__ void mma16816(float c[4], const unsigned a[4], unsigned b0, unsigned b1) {
    asm volatile("mma.sync.aligned.m16n8k16.row.col.f32.bf16.bf16.f32 "
                 "{%0,%1,%2,%3}, {%4,%5,%6,%7}, {%8,%9}, {%0,%1,%2,%3};"
                 : "+f"(c[0]), "+f"(c[1]), "+f"(c[2]), "+f"(c[3])
                 : "r"(a[0]), "r"(a[1]), "r"(a[2]), "r"(a[3]), "r"(b0), "r"(b1));
}
__device__ __forceinline__ void mma1688(float c[4], unsigned a0, unsigned a1, unsigned b0) {
    asm volatile("mma.sync.aligned.m16n8k8.row.col.f32.bf16.bf16.f32 "
                 "{%0,%1,%2,%3}, {%4,%5}, {%6}, {%0,%1,%2,%3};"
                 : "+f"(c[0]), "+f"(c[1]), "+f"(c[2]), "+f"(c[3])
                 : "r"(a0), "r"(a1), "r"(b0));
}
__device__ __forceinline__ float gelu_t(float t) {
    float u = 0.7978845608028654f * fmaf(0.044715f * t, t * t, t);
    return 0.5f * t * (1.f + ftanh(u));
}

// ---------------- prep: fold aff layers, repack to bf16 ----------------
__global__ void prep_kernel(
    const float* __restrict__ alpha1, const float* __restrict__ beta1, const float* __restrict__ color1,
    const float* __restrict__ qkv_w, const float* __restrict__ qkv_b,
    const float* __restrict__ alpha2, const float* __restrict__ beta2, const float* __restrict__ color2,
    const float* __restrict__ fc1_w, const float* __restrict__ fc1_b,
    const float* __restrict__ proj_w, const float* __restrict__ fc2_w)
{
    const int t = threadIdx.x;   // 256
    const float QSCL = 0.35355339059327373f * 1.4426950408889634f;
    for (int e = t; e < 48 * C; e += 256) {
        int j = e >> 4, c = e & 15;
        float acc = 0.f;
        for (int k = 0; k < C; k++)
            acc += qkv_w[j * C + k] * alpha1[k] * color1[k * C + c];
        gB_qkv[j * 24 + c] = __float2bfloat16((j < 16) ? acc * QSCL : acc);
    }
    if (t < 48) {
        float bb = qkv_b[t];
        for (int k = 0; k < C; k++) bb += qkv_w[t * C + k] * beta1[k];
        gQKVb[t] = (t < 16) ? bb * QSCL : bb;
    }
    for (int e = t; e < HID * C; e += 256) {
        int j = e >> 4, c = e & 15;
        float acc = 0.f;
        for (int k = 0; k < C; k++)
            acc += fc1_w[j * C + k] * alpha2[k] * color2[k * C + c];
        gB_fc1[j * 24 + c] = __float2bfloat16(acc);
    }
    if (t < HID) {
        float bb = fc1_b[t];
        for (int k = 0; k < C; k++) bb += fc1_w[t * C + k] * beta2[k];
        gFC1b[t] = bb;
    }
    for (int e = t; e < C * C; e += 256) {
        int j = e >> 4, c = e & 15;
        gB_proj[j * 24 + c] = __float2bfloat16(proj_w[j * C + c]);
    }
    for (int e = t; e < C * HID; e += 256) {
        int n = e >> 6, k = e & 63;
        gB_fc2[n * 72 + k] = __float2bfloat16(fc2_w[n * HID + k]);  // fc2_w is [C][HID]
    }
}

// ---------------- main fused kernel: 128 threads = 4 windows ----------------
__global__ __launch_bounds__(NTHR, 4) void swin_fused_kernel(
    const float* __restrict__ x,
    const float* __restrict__ pos_w, const float* __restrict__ pos_b,
    const float* __restrict__ proj_b, const float* __restrict__ fc2_b,
    float* __restrict__ out)
{
    // sh_dyn bytes layout (union with halo phase):
    //   [0, 16384)      s32[win][64 tok][16 ch] f32
    //   [16384, 24576)  K bf16 [win][2h][64 tok][8 d]      (tok stride 16B)
    //   [24576, 33792)  V^T bf16 [win][2h][8 d][72 tok pad] (d stride 144B)
    // halo phase uses floats [0, 5440)
    __shared__ __align__(16) float sh_dyn[8448];
    __shared__ __align__(4) __nv_bfloat16 sh_qkvw[48 * 24];
    __shared__ __align__(4) __nv_bfloat16 sh_fc1w[64 * 24];
    __shared__ __align__(4) __nv_bfloat16 sh_projw[16 * 24];
    __shared__ __align__(4) __nv_bfloat16 sh_fc2w[16 * 72];
    __shared__ __align__(16) float sh_posw[C * 9];
    __shared__ float sh_qkvb[48], sh_fc1b[HID];
    __shared__ float sh_projb[C], sh_fc2b[C], sh_posb[C];

    const int tid = threadIdx.x;
    const int b  = blockIdx.z;
    const int y0 = blockIdx.y * WS;
    const int x0 = blockIdx.x * (CTAW * WS);

    // ---- cooperative weight loads (bf16 arrays copied as u32) ----
    {
        const unsigned* s1 = (const unsigned*)gB_qkv;  unsigned* d1 = (unsigned*)sh_qkvw;
        const unsigned* s2 = (const unsigned*)gB_fc1;  unsigned* d2 = (unsigned*)sh_fc1w;
        const unsigned* s3 = (const unsigned*)gB_proj; unsigned* d3 = (unsigned*)sh_projw;
        const unsigned* s4 = (const unsigned*)gB_fc2;  unsigned* d4 = (unsigned*)sh_fc2w;
        for (int i = tid; i < 576; i += NTHR) d1[i] = s1[i];
        for (int i = tid; i < 768; i += NTHR) d2[i] = s2[i];
        for (int i = tid; i < 192; i += NTHR) d3[i] = s3[i];
        for (int i = tid; i < 576; i += NTHR) d4[i] = s4[i];
    }
    for (int i = tid; i < C * 9; i += NTHR) sh_posw[i] = pos_w[i];
    if (tid < 48) sh_qkvb[tid] = gQKVb[tid];
    if (tid < HID) sh_fc1b[tid] = gFC1b[tid];
    if (tid < C) {
        sh_projb[tid] = proj_b[tid];
        sh_fc2b[tid]  = fc2_b[tid];
        sh_posb[tid]  = pos_b[tid];
    }

    // ---- halo load: [C][10][34] f32 with zero padding ----
    const float* xb = x + (size_t)b * C * HW2;
#define HALO(c, r, cc) sh_dyn[(c) * 340 + (r) * 34 + (cc)]
    for (int i = tid; i < C * 340; i += NTHR) {
        int c = i / 340, rem = i - c * 340;
        int r = rem / 34, cc = rem - r * 34;
        int gy = y0 - 1 + r, gx = x0 - 1 + cc;
        float v = 0.f;
        if ((unsigned)gy < HH && (unsigned)gx < WW)
            v = xb[c * HW2 + gy * WW + gx];
        sh_dyn[i] = v;
    }
    __syncthreads();

    const int w = tid >> 5, lane = tid & 31;
    const int ty0 = lane >> 3, tx = lane & 7;   // conv token mapping (token = lane, lane+32)
    const int hc = w * 8 + tx;
    const int g = lane >> 2, t = lane & 3;      // mma fragment mapping

    // ---- depthwise 3x3 conv + residual + bias -> exact fp32 shortcut ----
    float s0[C], s1[C];
#pragma unroll
    for (int c = 0; c < C; c++) {
        float a0 = HALO(c, ty0 + 1, hc + 1) + sh_posb[c];
        float a1 = HALO(c, ty0 + 5, hc + 1) + sh_posb[c];
#pragma unroll
        for (int di = 0; di < 3; di++)
#pragma unroll
            for (int dj = 0; dj < 3; dj++) {
                float wgt = sh_posw[c * 9 + di * 3 + dj];
                a0 = fmaf(HALO(c, ty0 + di,     hc + dj), wgt, a0);
                a1 = fmaf(HALO(c, ty0 + 4 + di, hc + dj), wgt, a1);
            }
        s0[c] = a0; s1[c] = a1;
    }
    __syncthreads();   // all halo reads done -> sh_dyn reusable
#undef HALO

    // ---- shortcut to smem f32 [win][tok][16] ----
    {
        float4* d0 = (float4*)&sh_dyn[w * 1024 + lane * 16];
        float4* d1 = (float4*)&sh_dyn[w * 1024 + (lane + 32) * 16];
#pragma unroll
        for (int i = 0; i < 4; i++) {
            d0[i] = make_float4(s0[4*i], s0[4*i+1], s0[4*i+2], s0[4*i+3]);
            d1[i] = make_float4(s1[4*i], s1[4*i+1], s1[4*i+2], s1[4*i+3]);
        }
    }
    __syncwarp();

    char* dyn8 = (char*)sh_dyn;
    char* kbase = dyn8 + 16384 + w * 2048;   // + h*1024 + tok*16 + d*2
    char* vbase = dyn8 + 24576 + w * 2304;   // + h*1152 + d*144 + tok*2

    // ---- qkv via mma: A = shortcut [64x16], B = qkvw' [48x16] ----
    unsigned qf[2][4][2];   // Q bf16 A-frags per head per m-tile
#pragma unroll
    for (int mi = 0; mi < 4; mi++) {
        const int r = g + 16 * mi;
        float2 f0 = *(const float2*)&sh_dyn[w * 1024 + r * 16 + 2 * t];
        float2 f1 = *(const float2*)&sh_dyn[w * 1024 + (r + 8) * 16 + 2 * t];
        float2 f2 = *(const float2*)&sh_dyn[w * 1024 + r * 16 + 2 * t + 8];
        float2 f3 = *(const float2*)&sh_dyn[w * 1024 + (r + 8) * 16 + 2 * t + 8];
        unsigned A[4] = { bfp(f0.x, f0.y), bfp(f1.x, f1.y), bfp(f2.x, f2.y), bfp(f3.x, f3.y) };
#pragma unroll
        for (int nt = 0; nt < 6; nt++) {
            unsigned b0 = *(const unsigned*)&sh_qkvw[(8 * nt + g) * 24 + 2 * t];
            unsigned b1 = *(const unsigned*)&sh_qkvw[(8 * nt + g) * 24 + 2 * t + 8];
            float c[4] = {0.f, 0.f, 0.f, 0.f};
            mma16816(c, A, b0, b1);
            float2 bp = *(const float2*)&sh_qkvb[8 * nt + 2 * t];
            c[0] += bp.x; c[1] += bp.y; c[2] += bp.x; c[3] += bp.y;
            if (nt < 2) {                    // Q
                qf[nt][mi][0] = bfp(c[0], c[1]);
                qf[nt][mi][1] = bfp(c[2], c[3]);
            } else if (nt < 4) {             // K -> smem [tok][d]
                char* kb = kbase + (nt - 2) * 1024;
                *(unsigned*)(kb + r * 16 + 4 * t)       = bfp(c[0], c[1]);
                *(unsigned*)(kb + (r + 8) * 16 + 4 * t) = bfp(c[2], c[3]);
            } else {                         // V -> smem transposed [d][tok]
                char* vb = vbase + (nt - 4) * 1152;
                *(__nv_bfloat16*)(vb + (2*t)   * 144 + r * 2)       = __float2bfloat16(c[0]);
                *(__nv_bfloat16*)(vb + (2*t+1) * 144 + r * 2)       = __float2bfloat16(c[1]);
                *(__nv_bfloat16*)(vb + (2*t)   * 144 + (r + 8) * 2) = __float2bfloat16(c[2]);
                *(__nv_bfloat16*)(vb + (2*t+1) * 144 + (r + 8) * 2) = __float2bfloat16(c[3]);
            }
        }
    }
    __syncwarp();

    // ---- attention: S = Q@K^T (m16n8k8), exp, P@V (m16n8k16), deferred norm ----
    unsigned pao[2][4][2];   // attn output bf16 A-frags per head per m-tile
#pragma unroll
    for (int h = 0; h < HEADS; h++) {
        const char* kb_h = kbase + h * 1024;
        const char* vb_h = vbase + h * 1152;
        float rs[4][2];
        float oc[4][4];
#pragma unroll
        for (int mi = 0; mi < 4; mi++) {
            rs[mi][0] = 0.f; rs[mi][1] = 0.f;
#pragma unroll
            for (int j = 0; j < 4; j++) oc[mi][j] = 0.f;
        }
#pragma unroll
        for (int ki = 0; ki < 4; ki++) {
            unsigned vb0 = *(const unsigned*)(vb_h + g * 144 + (16 * ki + 2 * t) * 2);
            unsigned vb1 = *(const unsigned*)(vb_h + g * 144 + (16 * ki + 2 * t + 8) * 2);
            unsigned pa[4][4];
#pragma unroll
            for (int half = 0; half < 2; half++) {
                const int nt = 2 * ki + half;
                unsigned kb = *(const unsigned*)(kb_h + (nt * 8 + g) * 16 + 4 * t);
#pragma unroll
                for (int mi = 0; mi < 4; mi++) {
                    float sc[4] = {0.f, 0.f, 0.f, 0.f};
                    mma1688(sc, qf[h][mi][0], qf[h][mi][1], kb);
                    float e0 = fexp2(sc[0]), e1 = fexp2(sc[1]);
                    float e2 = fexp2(sc[2]), e3 = fexp2(sc[3]);
                    rs[mi][0] += e0 + e1;
                    rs[mi][1] += e2 + e3;
                    pa[mi][half * 2]     = bfp(e0, e1);
                    pa[mi][half * 2 + 1] = bfp(e2, e3);
                }
            }
#pragma unroll
            for (int mi = 0; mi < 4; mi++)
                mma16816(oc[mi], pa[mi], vb0, vb1);
        }
#pragma unroll
        for (int mi = 0; mi < 4; mi++) {
            float v0 = rs[mi][0];
            v0 += __shfl_xor_sync(0xffffffffu, v0, 1);
            v0 += __shfl_xor_sync(0xffffffffu, v0, 2);
            float v1 = rs[mi][1];
            v1 += __shfl_xor_sync(0xffffffffu, v1, 1);
            v1 += __shfl_xor_sync(0xffffffffu, v1, 2);
            float ri0 = frcp(v0), ri1 = frcp(v1);
            pao[h][mi][0] = bfp(oc[mi][0] * ri0, oc[mi][1] * ri0);
            pao[h][mi][1] = bfp(oc[mi][2] * ri1, oc[mi][3] * ri1);
        }
    }

    // ---- proj + residual (f32 from smem) -> x2 fragments ----
    float x2[4][2][4];
#pragma unroll
    for (int nt = 0; nt < 2; nt++) {
        unsigned b0 = *(const unsigned*)&sh_projw[(8 * nt + g) * 24 + 2 * t];
        unsigned b1 = *(const unsigned*)&sh_projw[(8 * nt + g) * 24 + 2 * t + 8];
        float2 bp = *(const float2*)&sh_projb[8 * nt + 2 * t];
#pragma unroll
        for (int mi = 0; mi < 4; mi++) {
            const int r = g + 16 * mi;
            float2 ra = *(const float2*)&sh_dyn[w * 1024 + r * 16 + 8 * nt + 2 * t];
            float2 rb = *(const float2*)&sh_dyn[w * 1024 + (r + 8) * 16 + 8 * nt + 2 * t];
            float* c = x2[mi][nt];
            c[0] = ra.x + bp.x; c[1] = ra.y + bp.y;
            c[2] = rb.x + bp.x; c[3] = rb.y + bp.y;
            unsigned A[4] = { pao[0][mi][0], pao[0][mi][1], pao[1][mi][0], pao[1][mi][1] };
            mma16816(c, A, b0, b1);
        }
    }

    // ---- MLP: fc1 (m16n8k16) -> GELU -> fc2 (accumulated over 4 k-steps) ----
    unsigned xa[4][4];
#pragma unroll
    for (int mi = 0; mi < 4; mi++) {
        xa[mi][0] = bfp(x2[mi][0][0], x2[mi][0][1]);
        xa[mi][1] = bfp(x2[mi][0][2], x2[mi][0][3]);
        xa[mi][2] = bfp(x2[mi][1][0], x2[mi][1][1]);
        xa[mi][3] = bfp(x2[mi][1][2], x2[mi][1][3]);
    }
    float oc2[4][2][4];
#pragma unroll
    for (int nt = 0; nt < 2; nt++) {
        float2 bp = *(const float2*)&sh_fc2b[8 * nt + 2 * t];
#pragma unroll
        for (int mi = 0; mi < 4; mi++) {
            oc2[mi][nt][0] = x2[mi][nt][0] + bp.x;
            oc2[mi][nt][1] = x2[mi][nt][1] + bp.y;
            oc2[mi][nt][2] = x2[mi][nt][2] + bp.x;
            oc2[mi][nt][3] = x2[mi][nt][3] + bp.y;
        }
    }
#pragma unroll
    for (int ki = 0; ki < 4; ki++) {
        unsigned ga[4][4];
#pragma unroll
        for (int half = 0; half < 2; half++) {
            const int nt = 2 * ki + half;
            unsigned f0 = *(const unsigned*)&sh_fc1w[(8 * nt + g) * 24 + 2 * t];
            unsigned f1 = *(const unsigned*)&sh_fc1w[(8 * nt + g) * 24 + 2 * t + 8];
            float2 hb = *(const float2*)&sh_fc1b[8 * nt + 2 * t];
#pragma unroll
            for (int mi = 0; mi < 4; mi++) {
                float hcv[4] = { hb.x, hb.y, hb.x, hb.y };
                mma16816(hcv, xa[mi], f0, f1);
                float g0 = gelu_t(hcv[0]), g1 = gelu_t(hcv[1]);
                float g2 = gelu_t(hcv[2]), g3 = gelu_t(hcv[3]);
                ga[mi][half * 2]     = bfp(g0, g1);
                ga[mi][half * 2 + 1] = bfp(g2, g3);
            }
        }
#pragma unroll
        for (int nt2 = 0; nt2 < 2; nt2++) {
            unsigned f20 = *(const unsigned*)&sh_fc2w[(8 * nt2 + g) * 72 + 16 * ki + 2 * t];
            unsigned f21 = *(const unsigned*)&sh_fc2w[(8 * nt2 + g) * 72 + 16 * ki + 2 * t + 8];
#pragma unroll
            for (int mi = 0; mi < 4; mi++)
                mma16816(oc2[mi][nt2], ga[mi], f20, f21);
        }
    }

    // ---- write out NCHW: token row = (g + 16mi [+8]) -> (ty = 2mi [+1], tx = g) ----
    float* ob = out + (size_t)b * C * HW2;
    const int gx = x0 + w * 8 + g;
#pragma unroll
    for (int mi = 0; mi < 4; mi++) {
        const int gya = y0 + 2 * mi;
#pragma unroll
        for (int nt = 0; nt < 2; nt++) {
            const int ch = 8 * nt + 2 * t;
            float* p = ob + (size_t)ch * HW2 + gya * WW + gx;
            p[0]          = oc2[mi][nt][0];
            p[HW2]        = oc2[mi][nt][1];
            p[WW]         = oc2[mi][nt][2];
            p[HW2 + WW]   = oc2[mi][nt][3];
        }
    }
}

extern "C" void kernel_launch(void* const* d_in, const int* in_sizes, int n_in,
                              void* d_out, int out_size) {
    (void)n_in; (void)out_size;
    const float* x      = (const float*)d_in[0];
    const float* pos_w  = (const float*)d_in[1];
    const float* pos_b  = (const float*)d_in[2];
    const float* alpha1 = (const float*)d_in[3];
    const float* beta1  = (const float*)d_in[4];
    const float* color1 = (const float*)d_in[5];
    const float* qkv_w  = (const float*)d_in[6];
    const float* qkv_b  = (const float*)d_in[7];
    const float* proj_w = (const float*)d_in[8];
    const float* proj_b = (const float*)d_in[9];
    const float* alpha2 = (const float*)d_in[10];
    const float* beta2  = (const float*)d_in[11];
    const float* color2 = (const float*)d_in[12];
    const float* fc1_w  = (const float*)d_in[13];
    const float* fc1_b  = (const float*)d_in[14];
    const float* fc2_w  = (const float*)d_in[15];
    const float* fc2_b  = (const float*)d_in[16];

    prep_kernel<<<1, 256>>>(alpha1, beta1, color1, qkv_w, qkv_b,
                            alpha2, beta2, color2, fc1_w, fc1_b, proj_w, fc2_w);

    int B = in_sizes[0] / (C * HH * WW);
    dim3 grid(WW / (CTAW * WS), HH / WS, B);
    swin_fused_kernel<<<grid, NTHR>>>(
        x, pos_w, pos_b, proj_b, fc2_b, (float*)d_out);
}

// round 17
// speedup vs baseline: 2.6355x; 1.6278x over previous
#include <cuda_runtime.h>
#include <cuda_bf16.h>

#define C 16
#define HEADS 2
#define HD 8
#define WS 8
#define HID 64
#define HH 512
#define WW 512
#define NTOK 64
#define CTAW 4
#define NTHR 128
#define HW2 (HH * WW)
#define HALO_BASE 4096        // float offset of halo region in sh_dyn
#define HALO_CSTR 341         // floats per channel plane (21 mod 32 -> conflict-free)

// ---- folded / repacked weights (prep kernel -> main kernel) ----
__device__ __nv_bfloat16 gB_qkv[48 * 24];   // qkv' (aff1 folded); Q rows pre-scaled hd^-.5*log2e
__device__ float         gQKVb[48];
__device__ __nv_bfloat16 gB_fc1[64 * 24];   // fc1' (aff2 folded)
__device__ float         gFC1b[64];
__device__ __nv_bfloat16 gB_proj[16 * 24];
__device__ __nv_bfloat16 gB_fc2[16 * 72];   // [out n][in k], k-stride 72

__device__ __forceinline__ float fexp2(float x) {
    float r; asm("ex2.approx.f32 %0, %1;" : "=f"(r) : "f"(x)); return r;
}
__device__ __forceinline__ float frcp(float x) {
    float r; asm("rcp.approx.f32 %0, %1;" : "=f"(r) : "f"(x)); return r;
}
__device__ __forceinline__ float ftanh(float x) {
    float r; asm("tanh.approx.f32 %0, %1;" : "=f"(r) : "f"(x)); return r;
}
// pack {lo, hi} floats -> bf16x2 (lo in lower 16 bits)
__device__ __forceinline__ unsigned bfp(float lo, float hi) {
    unsigned d; asm("cvt.rn.bf16x2.f32 %0, %1, %2;" : "=r"(d) : "f"(hi), "f"(lo)); return d;
}
__device__ __forceinline__ void mma16816(float c[4], const unsigned a[4], unsigned b0, unsigned b1) {
    asm volatile("mma.sync.aligned.m16n8k16.row.col.f32.bf16.bf16.f32 "
                 "{%0,%1,%2,%3}, {%4,%5,%6,%7}, {%8,%9}, {%0,%1,%2,%3};"
                 : "+f"(c[0]), "+f"(c[1]), "+f"(c[2]), "+f"(c[3])
                 : "r"(a[0]), "r"(a[1]), "r"(a[2]), "r"(a[3]), "r"(b0), "r"(b1));
}
__device__ __forceinline__ void mma1688(float c[4], unsigned a0, unsigned a1, unsigned b0) {
    asm volatile("mma.sync.aligned.m16n8k8.row.col.f32.bf16.bf16.f32 "
                 "{%0,%1,%2,%3}, {%4,%5}, {%6}, {%0,%1,%2,%3};"
                 : "+f"(c[0]), "+f"(c[1]), "+f"(c[2]), "+f"(c[3])
                 : "r"(a0), "r"(a1), "r"(b0));
}
__device__ __forceinline__ float gelu_t(float t) {
    float u = 0.7978845608028654f * fmaf(0.044715f * t, t * t, t);
    return 0.5f * t * (1.f + ftanh(u));
}

// ---------------- prep: fold aff layers, repack to bf16 ----------------
__global__ void prep_kernel(
    const float* __restrict__ alpha1, const float* __restrict__ beta1, const float* __restrict__ color1,
    const float* __restrict__ qkv_w, const float* __restrict__ qkv_b,
    const float* __restrict__ alpha2, const float* __restrict__ beta2, const float* __restrict__ color2,
    const float* __restrict__ fc1_w, const float* __restrict__ fc1_b,
    const float* __restrict__ proj_w, const float* __restrict__ fc2_w)
{
    const int t = threadIdx.x;   // 256
    const float QSCL = 0.35355339059327373f * 1.4426950408889634f;
    for (int e = t; e < 48 * C; e += 256) {
        int j = e >> 4, c = e & 15;
        float acc = 0.f;
        for (int k = 0; k < C; k++)
            acc += qkv_w[j * C + k] * alpha1[k] * color1[k * C + c];
        gB_qkv[j * 24 + c] = __float2bfloat16((j < 16) ? acc * QSCL : acc);
    }
    if (t < 48) {
        float bb = qkv_b[t];
        for (int k = 0; k < C; k++) bb += qkv_w[t * C + k] * beta1[k];
        gQKVb[t] = (t < 16) ? bb * QSCL : bb;
    }
    for (int e = t; e < HID * C; e += 256) {
        int j = e >> 4, c = e & 15;
        float acc = 0.f;
        for (int k = 0; k < C; k++)
            acc += fc1_w[j * C + k] * alpha2[k] * color2[k * C + c];
        gB_fc1[j * 24 + c] = __float2bfloat16(acc);
    }
    if (t < HID) {
        float bb = fc1_b[t];
        for (int k = 0; k < C; k++) bb += fc1_w[t * C + k] * beta2[k];
        gFC1b[t] = bb;
    }
    for (int e = t; e < C * C; e += 256) {
        int j = e >> 4, c = e & 15;
        gB_proj[j * 24 + c] = __float2bfloat16(proj_w[j * C + c]);
    }
    for (int e = t; e < C * HID; e += 256) {
        int n = e >> 6, k = e & 63;
        gB_fc2[n * 72 + k] = __float2bfloat16(fc2_w[n * HID + k]);  // fc2_w is [C][HID]
    }
}

// ---------------- main fused kernel: 128 threads = 4 windows ----------------
__global__ __launch_bounds__(NTHR, 4) void swin_fused_kernel(
    const float* __restrict__ x,
    const float* __restrict__ pos_w, const float* __restrict__ pos_b,
    const float* __restrict__ proj_b, const float* __restrict__ fc2_b,
    float* __restrict__ out)
{
    // sh_dyn float layout:
    //   [0, 4096)                 s32[win][64 tok][16 ch] f32
    //   [4096, 9552)              halo [16 ch][10 r][34 cc], channel stride 341 (phase 1)
    //   bytes [16384, 24576)      K bf16 [win][2h][64 tok][8 d]       (phase 2, halo dead)
    //   bytes [24576, 33792)      V^T bf16 [win][2h][8 d][72 tok pad] (phase 2)
    __shared__ __align__(16) float sh_dyn[9552];
    __shared__ __align__(4) __nv_bfloat16 sh_qkvw[48 * 24];
    __shared__ __align__(4) __nv_bfloat16 sh_fc1w[64 * 24];
    __shared__ __align__(4) __nv_bfloat16 sh_projw[16 * 24];
    __shared__ __align__(4) __nv_bfloat16 sh_fc2w[16 * 72];
    __shared__ __align__(16) float sh_posw[C * 9];
    __shared__ float sh_qkvb[48], sh_fc1b[HID];
    __shared__ float sh_projb[C], sh_fc2b[C], sh_posb[C];

    const int tid = threadIdx.x;
    const int b  = blockIdx.z;
    const int y0 = blockIdx.y * WS;
    const int x0 = blockIdx.x * (CTAW * WS);

    // ---- cooperative weight loads (bf16 arrays copied as u32) ----
    {
        const unsigned* s1 = (const unsigned*)gB_qkv;  unsigned* d1 = (unsigned*)sh_qkvw;
        const unsigned* s2 = (const unsigned*)gB_fc1;  unsigned* d2 = (unsigned*)sh_fc1w;
        const unsigned* s3 = (const unsigned*)gB_proj; unsigned* d3 = (unsigned*)sh_projw;
        const unsigned* s4 = (const unsigned*)gB_fc2;  unsigned* d4 = (unsigned*)sh_fc2w;
        for (int i = tid; i < 576; i += NTHR) d1[i] = s1[i];
        for (int i = tid; i < 768; i += NTHR) d2[i] = s2[i];
        for (int i = tid; i < 192; i += NTHR) d3[i] = s3[i];
        for (int i = tid; i < 576; i += NTHR) d4[i] = s4[i];
    }
    for (int i = tid; i < C * 9; i += NTHR) sh_posw[i] = pos_w[i];
    if (tid < 48) sh_qkvb[tid] = gQKVb[tid];
    if (tid < HID) sh_fc1b[tid] = gFC1b[tid];
    if (tid < C) {
        sh_projb[tid] = proj_b[tid];
        sh_fc2b[tid]  = fc2_b[tid];
        sh_posb[tid]  = pos_b[tid];
    }

    // ---- halo load: [16 ch][10 r][34 cc], div/mod once per (r,cc) pair ----
    const float* xb = x + (size_t)b * C * HW2;
    for (int p = tid; p < 340; p += NTHR) {
        int r = p / 34, cc = p - r * 34;
        int gy = y0 - 1 + r, gx = x0 - 1 + cc;
        bool ok = ((unsigned)gy < HH) && ((unsigned)gx < WW);
        const float* src = xb + (size_t)gy * WW + gx;
        float* dst = &sh_dyn[HALO_BASE + r * 34 + cc];
#pragma unroll
        for (int c = 0; c < C; c++) {
            float v = 0.f;
            if (ok) v = src[(size_t)c * HW2];
            dst[c * HALO_CSTR] = v;
        }
    }
    __syncthreads();

    const int w = tid >> 5, lane = tid & 31;
    const int g = lane >> 2, t = lane & 3;      // mma fragment mapping

    // ---- depthwise 3x3 conv + residual + bias, streamed to s32 smem ----
    // lane -> channel = lane>>1, row-half = lane&1 (output rows rh*4 .. rh*4+3)
    {
        const int cch = lane >> 1, rh = lane & 1;
        float wr[9];
#pragma unroll
        for (int i = 0; i < 9; i++) wr[i] = sh_posw[cch * 9 + i];
        const float pb = sh_posb[cch];
        const float* hb = &sh_dyn[HALO_BASE + cch * HALO_CSTR + w * 8];
        float ra[10], rb[10], rc[10];
#pragma unroll
        for (int col = 0; col < 10; col++) {
            ra[col] = hb[(rh * 4 + 0) * 34 + col];
            rb[col] = hb[(rh * 4 + 1) * 34 + col];
            rc[col] = hb[(rh * 4 + 2) * 34 + col];
        }
#pragma unroll
        for (int q = 0; q < 4; q++) {
            const int tok = (rh * 4 + q) * 8;
#pragma unroll
            for (int j = 0; j < 8; j++) {
                float a = pb + rb[j + 1];                 // residual center + bias
                a = fmaf(ra[j],     wr[0], a);
                a = fmaf(ra[j + 1], wr[1], a);
                a = fmaf(ra[j + 2], wr[2], a);
                a = fmaf(rb[j],     wr[3], a);
                a = fmaf(rb[j + 1], wr[4], a);
                a = fmaf(rb[j + 2], wr[5], a);
                a = fmaf(rc[j],     wr[6], a);
                a = fmaf(rc[j + 1], wr[7], a);
                a = fmaf(rc[j + 2], wr[8], a);
                sh_dyn[w * 1024 + (tok + j) * 16 + cch] = a;
            }
            if (q < 3) {
#pragma unroll
                for (int col = 0; col < 10; col++) {
                    ra[col] = rb[col];
                    rb[col] = rc[col];
                    rc[col] = hb[(rh * 4 + q + 3) * 34 + col];
                }
            }
        }
    }
    __syncthreads();   // s32 complete; halo dead -> K/V region reusable

    char* dyn8 = (char*)sh_dyn;
    char* kbase = dyn8 + 16384 + w * 2048;   // + h*1024 + tok*16 + d*2
    char* vbase = dyn8 + 24576 + w * 2304;   // + h*1152 + d*144 + tok*2

    // ---- qkv via mma: A = shortcut [64x16], B = qkvw' [48x16] ----
    unsigned qf[2][4][2];   // Q bf16 A-frags per head per m-tile
#pragma unroll
    for (int mi = 0; mi < 4; mi++) {
        const int r = g + 16 * mi;
        float2 f0 = *(const float2*)&sh_dyn[w * 1024 + r * 16 + 2 * t];
        float2 f1 = *(const float2*)&sh_dyn[w * 1024 + (r + 8) * 16 + 2 * t];
        float2 f2 = *(const float2*)&sh_dyn[w * 1024 + r * 16 + 2 * t + 8];
        float2 f3 = *(const float2*)&sh_dyn[w * 1024 + (r + 8) * 16 + 2 * t + 8];
        unsigned A[4] = { bfp(f0.x, f0.y), bfp(f1.x, f1.y), bfp(f2.x, f2.y), bfp(f3.x, f3.y) };
#pragma unroll
        for (int nt = 0; nt < 6; nt++) {
            unsigned b0 = *(const unsigned*)&sh_qkvw[(8 * nt + g) * 24 + 2 * t];
            unsigned b1 = *(const unsigned*)&sh_qkvw[(8 * nt + g) * 24 + 2 * t + 8];
            float c[4] = {0.f, 0.f, 0.f, 0.f};
            mma16816(c, A, b0, b1);
            float2 bp = *(const float2*)&sh_qkvb[8 * nt + 2 * t];
            c[0] += bp.x; c[1] += bp.y; c[2] += bp.x; c[3] += bp.y;
            if (nt < 2) {                    // Q
                qf[nt][mi][0] = bfp(c[0], c[1]);
                qf[nt][mi][1] = bfp(c[2], c[3]);
            } else if (nt < 4) {             // K -> smem [tok][d]
                char* kb = kbase + (nt - 2) * 1024;
                *(unsigned*)(kb + r * 16 + 4 * t)       = bfp(c[0], c[1]);
                *(unsigned*)(kb + (r + 8) * 16 + 4 * t) = bfp(c[2], c[3]);
            } else {                         // V -> smem transposed [d][tok]
                char* vb = vbase + (nt - 4) * 1152;
                *(__nv_bfloat16*)(vb + (2*t)   * 144 + r * 2)       = __float2bfloat16(c[0]);
                *(__nv_bfloat16*)(vb + (2*t+1) * 144 + r * 2)       = __float2bfloat16(c[1]);
                *(__nv_bfloat16*)(vb + (2*t)   * 144 + (r + 8) * 2) = __float2bfloat16(c[2]);
                *(__nv_bfloat16*)(vb + (2*t+1) * 144 + (r + 8) * 2) = __float2bfloat16(c[3]);
            }
        }
    }
    __syncwarp();

    // ---- attention: S = Q@K^T (m16n8k8), exp, P@V (m16n8k16), deferred norm ----
    unsigned pao[2][4][2];   // attn output bf16 A-frags per head per m-tile
#pragma unroll
    for (int h = 0; h < HEADS; h++) {
        const char* kb_h = kbase + h * 1024;
        const char* vb_h = vbase + h * 1152;
        float rs[4][2];
        float oc[4][4];
#pragma unroll
        for (int mi = 0; mi < 4; mi++) {
            rs[mi][0] = 0.f; rs[mi][1] = 0.f;
#pragma unroll
            for (int j = 0; j < 4; j++) oc[mi][j] = 0.f;
        }
#pragma unroll
        for (int ki = 0; ki < 4; ki++) {
            unsigned vb0 = *(const unsigned*)(vb_h + g * 144 + (16 * ki + 2 * t) * 2);
            unsigned vb1 = *(const unsigned*)(vb_h + g * 144 + (16 * ki + 2 * t + 8) * 2);
            unsigned pa[4][4];
#pragma unroll
            for (int half = 0; half < 2; half++) {
                const int nt = 2 * ki + half;
                unsigned kb = *(const unsigned*)(kb_h + (nt * 8 + g) * 16 + 4 * t);
#pragma unroll
                for (int mi = 0; mi < 4; mi++) {
                    float sc[4] = {0.f, 0.f, 0.f, 0.f};
                    mma1688(sc, qf[h][mi][0], qf[h][mi][1], kb);
                    float e0 = fexp2(sc[0]), e1 = fexp2(sc[1]);
                    float e2 = fexp2(sc[2]), e3 = fexp2(sc[3]);
                    rs[mi][0] += e0 + e1;
                    rs[mi][1] += e2 + e3;
                    pa[mi][half * 2]     = bfp(e0, e1);
                    pa[mi][half * 2 + 1] = bfp(e2, e3);
                }
            }
#pragma unroll
            for (int mi = 0; mi < 4; mi++)
                mma16816(oc[mi], pa[mi], vb0, vb1);
        }
#pragma unroll
        for (int mi = 0; mi < 4; mi++) {
            float v0 = rs[mi][0];
            v0 += __shfl_xor_sync(0xffffffffu, v0, 1);
            v0 += __shfl_xor_sync(0xffffffffu, v0, 2);
            float v1 = rs[mi][1];
            v1 += __shfl_xor_sync(0xffffffffu, v1, 1);
            v1 += __shfl_xor_sync(0xffffffffu, v1, 2);
            float ri0 = frcp(v0), ri1 = frcp(v1);
            pao[h][mi][0] = bfp(oc[mi][0] * ri0, oc[mi][1] * ri0);
            pao[h][mi][1] = bfp(oc[mi][2] * ri1, oc[mi][3] * ri1);
        }
    }

    // ---- proj + residual (f32 from smem) -> x2 fragments ----
    float x2[4][2][4];
#pragma unroll
    for (int nt = 0; nt < 2; nt++) {
        unsigned b0 = *(const unsigned*)&sh_projw[(8 * nt + g) * 24 + 2 * t];
        unsigned b1 = *(const unsigned*)&sh_projw[(8 * nt + g) * 24 + 2 * t + 8];
        float2 bp = *(const float2*)&sh_projb[8 * nt + 2 * t];
#pragma unroll
        for (int mi = 0; mi < 4; mi++) {
            const int r = g + 16 * mi;
            float2 ra = *(const float2*)&sh_dyn[w * 1024 + r * 16 + 8 * nt + 2 * t];
            float2 rb = *(const float2*)&sh_dyn[w * 1024 + (r + 8) * 16 + 8 * nt + 2 * t];
            float* c = x2[mi][nt];
            c[0] = ra.x + bp.x; c[1] = ra.y + bp.y;
            c[2] = rb.x + bp.x; c[3] = rb.y + bp.y;
            unsigned A[4] = { pao[0][mi][0], pao[0][mi][1], pao[1][mi][0], pao[1][mi][1] };
            mma16816(c, A, b0, b1);
        }
    }

    // ---- MLP: fc1 (m16n8k16) -> GELU -> fc2 (accumulated over 4 k-steps) ----
    unsigned xa[4][4];
#pragma unroll
    for (int mi = 0; mi < 4; mi++) {
        xa[mi][0] = bfp(x2[mi][0][0], x2[mi][0][1]);
        xa[mi][1] = bfp(x2[mi][0][2], x2[mi][0][3]);
        xa[mi][2] = bfp(x2[mi][1][0], x2[mi][1][1]);
        xa[mi][3] = bfp(x2[mi][1][2], x2[mi][1][3]);
    }
    float oc2[4][2][4];
#pragma unroll
    for (int nt = 0; nt < 2; nt++) {
        float2 bp = *(const float2*)&sh_fc2b[8 * nt + 2 * t];
#pragma unroll
        for (int mi = 0; mi < 4; mi++) {
            oc2[mi][nt][0] = x2[mi][nt][0] + bp.x;
            oc2[mi][nt][1] = x2[mi][nt][1] + bp.y;
            oc2[mi][nt][2] = x2[mi][nt][2] + bp.x;
            oc2[mi][nt][3] = x2[mi][nt][3] + bp.y;
        }
    }
#pragma unroll
    for (int ki = 0; ki < 4; ki++) {
        unsigned ga[4][4];
#pragma unroll
        for (int half = 0; half < 2; half++) {
            const int nt = 2 * ki + half;
            unsigned f0 = *(const unsigned*)&sh_fc1w[(8 * nt + g) * 24 + 2 * t];
            unsigned f1 = *(const unsigned*)&sh_fc1w[(8 * nt + g) * 24 + 2 * t + 8];
            float2 hb = *(const float2*)&sh_fc1b[8 * nt + 2 * t];
#pragma unroll
            for (int mi = 0; mi < 4; mi++) {
                float hcv[4] = { hb.x, hb.y, hb.x, hb.y };
                mma16816(hcv, xa[mi], f0, f1);
                float g0 = gelu_t(hcv[0]), g1 = gelu_t(hcv[1]);
                float g2 = gelu_t(hcv[2]), g3 = gelu_t(hcv[3]);
                ga[mi][half * 2]     = bfp(g0, g1);
                ga[mi][half * 2 + 1] = bfp(g2, g3);
            }
        }
#pragma unroll
        for (int nt2 = 0; nt2 < 2; nt2++) {
            unsigned f20 = *(const unsigned*)&sh_fc2w[(8 * nt2 + g) * 72 + 16 * ki + 2 * t];
            unsigned f21 = *(const unsigned*)&sh_fc2w[(8 * nt2 + g) * 72 + 16 * ki + 2 * t + 8];
#pragma unroll
            for (int mi = 0; mi < 4; mi++)
                mma16816(oc2[mi][nt2], ga[mi], f20, f21);
        }
    }

    // ---- write out NCHW: token row = (g + 16mi [+8]) -> (ty = 2mi [+1], tx = g) ----
    float* ob = out + (size_t)b * C * HW2;
    const int gx = x0 + w * 8 + g;
#pragma unroll
    for (int mi = 0; mi < 4; mi++) {
        const int gya = y0 + 2 * mi;
#pragma unroll
        for (int nt = 0; nt < 2; nt++) {
            const int ch = 8 * nt + 2 * t;
            float* p = ob + (size_t)ch * HW2 + gya * WW + gx;
            p[0]          = oc2[mi][nt][0];
            p[HW2]        = oc2[mi][nt][1];
            p[WW]         = oc2[mi][nt][2];
            p[HW2 + WW]   = oc2[mi][nt][3];
        }
    }
}

extern "C" void kernel_launch(void* const* d_in, const int* in_sizes, int n_in,
                              void* d_out, int out_size) {
    (void)n_in; (void)out_size;
    const float* x      = (const float*)d_in[0];
    const float* pos_w  = (const float*)d_in[1];
    const float* pos_b  = (const float*)d_in[2];
    const float* alpha1 = (const float*)d_in[3];
    const float* beta1  = (const float*)d_in[4];
    const float* color1 = (const float*)d_in[5];
    const float* qkv_w  = (const float*)d_in[6];
    const float* qkv_b  = (const float*)d_in[7];
    const float* proj_w = (const float*)d_in[8];
    const float* proj_b = (const float*)d_in[9];
    const float* alpha2 = (const float*)d_in[10];
    const float* beta2  = (const float*)d_in[11];
    const float* color2 = (const float*)d_in[12];
    const float* fc1_w  = (const float*)d_in[13];
    const float* fc1_b  = (const float*)d_in[14];
    const float* fc2_w  = (const float*)d_in[15];
    const float* fc2_b  = (const float*)d_in[16];

    prep_kernel<<<1, 256>>>(alpha1, beta1, color1, qkv_w, qkv_b,
                            alpha2, beta2, color2, fc1_w, fc1_b, proj_w, fc2_w);

    int B = in_sizes[0] / (C * HH * WW);
    dim3 grid(WW / (CTAW * WS), HH / WS, B);
    swin_fused_kernel<<<grid, NTHR>>>(
        x, pos_w, pos_b, proj_b, fc2_b, (float*)d_out);
}